// round 16
// baseline (speedup 1.0000x reference)
#include <cuda_runtime.h>
#include <cuda_bf16.h>
#include <cstdint>

#define N_MAX 100000
#define E_MAX 1700000
#define D 128
#define BB 1024
#define NB_MAX 128      // >= ceil(N_MAX/BB) = 98

// ---------------- scratch (static device globals) ----------------
__device__ __align__(16) float g_buf[N_MAX * D];            // g[u] = dinv[u]*(X@W)[u]
__device__ __align__(16) __nv_bfloat16 g_xh[N_MAX * D];     // activation hi split
__device__ __align__(16) __nv_bfloat16 g_xl[N_MAX * D];     // activation lo split
__device__ float g_dinv[N_MAX];
__device__ int   g_cnt[N_MAX];                              // ZERO on entry (re-zeroed in gemm L1 fill phase)
__device__ int   g_rowptr[N_MAX + 1];
__device__ int   g_cursor[N_MAX];
__device__ int   g_blocksum[NB_MAX];
__device__ int   g_blockoff[NB_MAX];
__device__ int   g_csr[E_MAX];
__device__ __align__(16) __nv_bfloat16 g_wt_hi[3 * D * D];  // W^T hi split [l][n][k]
__device__ __align__(16) __nv_bfloat16 g_wt_lo[3 * D * D];  // W^T lo split
__device__ unsigned g_bar_cnt = 0;
__device__ unsigned g_bar_gen = 0;

// ---------------- helpers ----------------
__device__ __forceinline__ uint32_t smem_u32(const void* p) {
    uint32_t a;
    asm("{ .reg .u64 t; cvta.to.shared.u64 t, %1; cvt.u32.u64 %0, t; }" : "=r"(a) : "l"(p));
    return a;
}
__device__ __forceinline__ void cp_async16(uint32_t saddr, const void* gptr, bool valid) {
    int sz = valid ? 16 : 0;
    asm volatile("cp.async.cg.shared.global [%0], [%1], 16, %2;"
                 :: "r"(saddr), "l"(gptr), "r"(sz));
}
#define CP_COMMIT()    asm volatile("cp.async.commit_group;")
#define CP_WAIT_ALL()  asm volatile("cp.async.wait_all;" ::: "memory")
#define CP_WAIT_1()    asm volatile("cp.async.wait_group 1;" ::: "memory")

__device__ __forceinline__ void ldsm_x4(uint32_t* r, uint32_t saddr) {
    asm volatile("ldmatrix.sync.aligned.m8n8.x4.shared.b16 {%0,%1,%2,%3}, [%4];"
                 : "=r"(r[0]), "=r"(r[1]), "=r"(r[2]), "=r"(r[3]) : "r"(saddr));
}

__device__ __forceinline__ void split_store(float x, float y, float z, float w,
                                            __nv_bfloat16* ph, __nv_bfloat16* pl) {
    __nv_bfloat162 h01, h23, l01, l23;
    h01.x = __float2bfloat16(x); h01.y = __float2bfloat16(y);
    h23.x = __float2bfloat16(z); h23.y = __float2bfloat16(w);
    l01.x = __float2bfloat16(x - __bfloat162float(h01.x));
    l01.y = __float2bfloat16(y - __bfloat162float(h01.y));
    l23.x = __float2bfloat16(z - __bfloat162float(h23.x));
    l23.y = __float2bfloat16(w - __bfloat162float(h23.y));
    *(uint2*)ph = make_uint2(*(uint32_t*)&h01, *(uint32_t*)&h23);
    *(uint2*)pl = make_uint2(*(uint32_t*)&l01, *(uint32_t*)&l23);
}

// sense-reversing grid barrier; single-wave residency required
__device__ __forceinline__ void grid_barrier(int nblocks) {
    __syncthreads();
    if (threadIdx.x == 0) {
        unsigned gen = atomicAdd(&g_bar_gen, 0u);
        __threadfence();
        unsigned old = atomicAdd(&g_bar_cnt, 1u);
        if (old == (unsigned)nblocks - 1u) {
            atomicExch(&g_bar_cnt, 0u);
            __threadfence();
            atomicAdd(&g_bar_gen, 1u);
        } else {
            while (atomicAdd(&g_bar_gen, 0u) == gen) { }
        }
        __threadfence();
    }
    __syncthreads();
}

// ---------------- fused prep: W/X splits + degree histogram ----------------
__global__ void prep_cnt(const float* __restrict__ X,
                         const float* __restrict__ W0, const float* __restrict__ W1,
                         const float* __restrict__ W2,
                         const int* __restrict__ dst, int n, int E) {
    int gi  = blockIdx.x * blockDim.x + threadIdx.x;
    int gsz = gridDim.x * blockDim.x;
    int total4 = n * (D / 4);
    for (int i = gi; i < total4; i += gsz) {
        float4 v = *(const float4*)&X[(size_t)i * 4];
        split_store(v.x, v.y, v.z, v.w, &g_xh[(size_t)i * 4], &g_xl[(size_t)i * 4]);
    }
    for (int i = gi; i < 3 * D * D; i += gsz) {
        int l = i / (D * D);
        int r = i % (D * D);
        int nn = r >> 7, kk = r & 127;
        const float* W = (l == 0) ? W0 : ((l == 1) ? W1 : W2);
        float f = W[kk * D + nn];
        __nv_bfloat16 h = __float2bfloat16(f);
        g_wt_hi[i] = h;
        g_wt_lo[i] = __float2bfloat16(f - __bfloat162float(h));
    }
    for (int i = gi; i < E; i += gsz) atomicAdd(&g_cnt[__ldg(&dst[i])], 1);
}

// ---------------- fused scan: rowptr/cursor/dinv ----------------
__global__ __launch_bounds__(BB)
void scan_all(int n, int nblocks) {
    __shared__ int s[BB];
    __shared__ int s2[NB_MAX];
    const int tid = threadIdx.x;
    const int b   = blockIdx.x;
    const int gi  = b * BB + tid;

    int v = (gi < n) ? g_cnt[gi] : 0;
    s[tid] = v;
    __syncthreads();
    #pragma unroll
    for (int off = 1; off < BB; off <<= 1) {
        int t = (tid >= off) ? s[tid - off] : 0;
        __syncthreads();
        s[tid] += t;
        __syncthreads();
    }
    int incl = s[tid];
    if (tid == BB - 1) g_blocksum[b] = incl;
    grid_barrier(nblocks);

    if (b == 0) {
        int u = (tid < nblocks) ? g_blocksum[tid] : 0;
        if (tid < NB_MAX) s2[tid] = u;
        __syncthreads();
        #pragma unroll
        for (int off = 1; off < NB_MAX; off <<= 1) {
            int t = (tid >= off && tid < NB_MAX) ? s2[tid - off] : 0;
            __syncthreads();
            if (tid < NB_MAX) s2[tid] += t;
            __syncthreads();
        }
        if (tid < nblocks) g_blockoff[tid] = s2[tid] - u;
        if (tid == nblocks - 1) g_rowptr[n] = s2[tid];
    }
    grid_barrier(nblocks);

    if (gi < n) {
        int excl = incl - v + g_blockoff[b];
        g_rowptr[gi] = excl;
        g_cursor[gi] = excl;
        g_dinv[gi]   = rsqrtf((float)(v + 1));
    }
}

// ---------------- persistent bf16x3 GEMM (+ CSR fill phase on layer 0) ----------------
#define PITCH 68
#define AR 32
#define SM_B (128 * PITCH)
#define SM_A (AR * PITCH)
#define SM_TOTAL_B ((2 * SM_B + 4 * SM_A) * 4)   // 104448 bytes -> 2 CTAs/SM
#define GEMM_GRID 296

__device__ __forceinline__ void mma16816(float* c, const uint32_t* a, const uint32_t* b) {
    asm volatile(
        "mma.sync.aligned.m16n8k16.row.col.f32.bf16.bf16.f32 "
        "{%0,%1,%2,%3}, {%4,%5,%6,%7}, {%8,%9}, {%0,%1,%2,%3};"
        : "+f"(c[0]), "+f"(c[1]), "+f"(c[2]), "+f"(c[3])
        : "r"(a[0]), "r"(a[1]), "r"(a[2]), "r"(a[3]), "r"(b[0]), "r"(b[1]));
}

template <bool FILL>
__global__ __launch_bounds__(256, 2)
void gemm_mma(int layer, int nrows, int ntiles,
              const int* __restrict__ esrc, const int* __restrict__ edst, int E) {
    extern __shared__ uint32_t smem[];
    uint32_t* Bh = smem;
    uint32_t* Bl = Bh + SM_B;

    const int tid = threadIdx.x;
    const uint32_t sb  = smem_u32(smem);
    const uint32_t sBh = sb;
    const uint32_t sBl = sb + SM_B * 4;
    const uint32_t sA  = sb + 2 * SM_B * 4;

    {
        const __nv_bfloat16* wh = &g_wt_hi[layer * D * D];
        const __nv_bfloat16* wl = &g_wt_lo[layer * D * D];
        #pragma unroll
        for (int i = 0; i < 8; i++) {
            int id = tid + i * 256;
            int n  = id >> 4;
            int q  = id & 15;
            size_t gof = (size_t)n * D + q * 8;
            uint32_t so = (n * PITCH + q * 4) * 4;
            cp_async16(sBh + so, &wh[gof], true);
            cp_async16(sBl + so, &wl[gof], true);
        }
    }
    CP_COMMIT();

    auto loadA = [&](int buf, int t) {
        int m0 = t * AR;
        uint32_t base = sA + (uint32_t)buf * (2 * SM_A * 4);
        #pragma unroll
        for (int i = 0; i < 2; i++) {
            int id  = tid + i * 256;
            int row = id >> 4;
            int q   = id & 15;
            int gr  = m0 + row;
            bool ok = gr < nrows;
            size_t gof = (size_t)gr * D + q * 8;
            uint32_t so = (row * PITCH + q * 4) * 4;
            cp_async16(base + so, &g_xh[gof], ok);
            cp_async16(base + SM_A * 4 + so, &g_xl[gof], ok);
        }
    };

    const int t0     = blockIdx.x;
    const int stride = gridDim.x;
    if (t0 < ntiles) loadA(0, t0);
    CP_COMMIT();

    const int wid  = tid >> 5;
    const int lane = tid & 31;
    const int g    = lane >> 2;
    const int tig  = lane & 3;
    const int wn   = wid * 16;

    const int lm_m   = lane >> 3;
    const int lm_row = ((lm_m & 1) << 3) + (lane & 7);
    const int lm_kc  = (lm_m >> 1) << 2;
    const uint32_t lm_off = (uint32_t)(lm_row * PITCH + lm_kc) * 4;

    CP_WAIT_1();
    __syncthreads();

    uint32_t breg[2][8][2][2];
    #pragma unroll
    for (int sp = 0; sp < 2; sp++) {
        const uint32_t* Bp = sp ? Bl : Bh;
        #pragma unroll
        for (int step = 0; step < 8; step++) {
            #pragma unroll
            for (int nt = 0; nt < 2; nt++) {
                int c = wn + nt * 8 + g;
                breg[sp][step][nt][0] = Bp[c * PITCH + step * 8 + tig];
                breg[sp][step][nt][1] = Bp[c * PITCH + step * 8 + tig + 4];
            }
        }
    }

    int buf = 0;
    for (int t = t0; t < ntiles; t += stride) {
        int nxt = t + stride;
        if (nxt < ntiles) loadA(buf ^ 1, nxt);
        CP_COMMIT();
        CP_WAIT_1();
        __syncthreads();

        const uint32_t aHi = sA + (uint32_t)buf * (2 * SM_A * 4) + lm_off;
        const uint32_t aLo = aHi + SM_A * 4;

        float acc[2][2][4];
        #pragma unroll
        for (int mt = 0; mt < 2; mt++)
            #pragma unroll
            for (int nt = 0; nt < 2; nt++)
                #pragma unroll
                for (int e = 0; e < 4; e++) acc[mt][nt][e] = 0.f;

        #pragma unroll
        for (int step = 0; step < 8; step++) {
            const uint32_t koff = (uint32_t)(step * 8) * 4;
            uint32_t ah[2][4], al[2][4];
            #pragma unroll
            for (int mt = 0; mt < 2; mt++)
                ldsm_x4(ah[mt], aHi + (uint32_t)(mt * 16 * PITCH) * 4 + koff);
            #pragma unroll
            for (int mt = 0; mt < 2; mt++)
                ldsm_x4(al[mt], aLo + (uint32_t)(mt * 16 * PITCH) * 4 + koff);
            #pragma unroll
            for (int mt = 0; mt < 2; mt++) {
                #pragma unroll
                for (int nt = 0; nt < 2; nt++) {
                    mma16816(acc[mt][nt], ah[mt], breg[0][step][nt]);
                    mma16816(acc[mt][nt], ah[mt], breg[1][step][nt]);
                    mma16816(acc[mt][nt], al[mt], breg[0][step][nt]);
                }
            }
        }

        int m0 = t * AR;
        #pragma unroll
        for (int mt = 0; mt < 2; mt++) {
            #pragma unroll
            for (int half = 0; half < 2; half++) {
                int row = m0 + mt * 16 + g + half * 8;
                if (row < nrows) {
                    float dv = g_dinv[row];
                    #pragma unroll
                    for (int nt = 0; nt < 2; nt++) {
                        float2 v;
                        v.x = dv * acc[mt][nt][half * 2 + 0];
                        v.y = dv * acc[mt][nt][half * 2 + 1];
                        *(float2*)&g_buf[(size_t)row * D + wn + nt * 8 + tig * 2] = v;
                    }
                }
            }
        }
        __syncthreads();
        buf ^= 1;
    }
    CP_WAIT_ALL();

    // --- layer-0 tail: CSR fill + cnt re-zero (latency-bound; hides under gemm tail) ---
    if (FILL) {
        const int base = blockIdx.x * 256 + tid;
        const int gsz  = GEMM_GRID * 256;
        for (int i = base; i < E; i += gsz) {
            int d = __ldg(&edst[i]);
            int pos = atomicAdd(&g_cursor[d], 1);
            g_csr[pos] = __ldg(&esrc[i]);
        }
        for (int i = base; i < nrows; i += gsz) g_cnt[i] = 0;  // ready for next call
    }
}

// ---------------- aggregate ----------------
template <bool TO_GX>
__global__ __launch_bounds__(256)
void aggregate(const float* __restrict__ bias, float* __restrict__ outp, int n) {
    int w    = (blockIdx.x * blockDim.x + threadIdx.x) >> 5;
    int lane = threadIdx.x & 31;
    if (w >= n) return;

    int beg = g_rowptr[w];
    int end = g_rowptr[w + 1];
    size_t col = (size_t)lane * 4;

    float4 acc = *(const float4*)&g_buf[(size_t)w * D + col];   // self-loop

    int e = beg;
    for (; e + 4 <= end; e += 4) {
        int s0 = __ldg(&g_csr[e]);
        int s1 = __ldg(&g_csr[e + 1]);
        int s2 = __ldg(&g_csr[e + 2]);
        int s3 = __ldg(&g_csr[e + 3]);
        float4 v0 = *(const float4*)&g_buf[(size_t)s0 * D + col];
        float4 v1 = *(const float4*)&g_buf[(size_t)s1 * D + col];
        float4 v2 = *(const float4*)&g_buf[(size_t)s2 * D + col];
        float4 v3 = *(const float4*)&g_buf[(size_t)s3 * D + col];
        acc.x += (v0.x + v1.x) + (v2.x + v3.x);
        acc.y += (v0.y + v1.y) + (v2.y + v3.y);
        acc.z += (v0.z + v1.z) + (v2.z + v3.z);
        acc.w += (v0.w + v1.w) + (v2.w + v3.w);
    }
    for (; e < end; e++) {
        int s0 = __ldg(&g_csr[e]);
        float4 v0 = *(const float4*)&g_buf[(size_t)s0 * D + col];
        acc.x += v0.x; acc.y += v0.y; acc.z += v0.z; acc.w += v0.w;
    }

    float dv = g_dinv[w];
    float4 b = *(const float4*)&bias[col];
    float4 r;
    r.x = fmaxf(fmaf(dv, acc.x, b.x), 0.f);
    r.y = fmaxf(fmaf(dv, acc.y, b.y), 0.f);
    r.z = fmaxf(fmaf(dv, acc.z, b.z), 0.f);
    r.w = fmaxf(fmaf(dv, acc.w, b.w), 0.f);

    if (TO_GX) {
        size_t off = (size_t)w * D + col;
        split_store(r.x, r.y, r.z, r.w, &g_xh[off], &g_xl[off]);
    } else {
        *(float4*)&outp[(size_t)w * D + col] = r;
    }
}

// ---------------- launch ----------------
extern "C" void kernel_launch(void* const* d_in, const int* in_sizes, int n_in,
                              void* d_out, int out_size) {
    const float* node_fts = (const float*)d_in[0];
    const int*   edge     = (const int*)d_in[1];   // int32
    const float* W[3] = { (const float*)d_in[2], (const float*)d_in[4], (const float*)d_in[6] };
    const float* B[3] = { (const float*)d_in[3], (const float*)d_in[5], (const float*)d_in[7] };

    const int nrows = in_sizes[0] / D;
    const int E     = in_sizes[1] / 2;
    const int* src  = edge;
    const int* dst  = edge + E;

    static bool attr_done = false;
    if (!attr_done) {
        cudaFuncSetAttribute(gemm_mma<true>,  cudaFuncAttributeMaxDynamicSharedMemorySize, SM_TOTAL_B);
        cudaFuncSetAttribute(gemm_mma<false>, cudaFuncAttributeMaxDynamicSharedMemorySize, SM_TOTAL_B);
        attr_done = true;
    }

    const int nblocks = (nrows + BB - 1) / BB;

    // build: 2 launches (fill fused into gemm L1)
    prep_cnt<<<(nrows * (D / 4) + 255) / 256, 256>>>(node_fts, W[0], W[1], W[2], dst, nrows, E);
    scan_all<<<nblocks, BB>>>(nrows, nblocks);

    const int ntiles     = (nrows + AR - 1) / AR;
    const int agg_blocks = (nrows * 32 + 255) / 256;

    // Layer 1 (gemm + CSR fill fused)
    gemm_mma<true><<<GEMM_GRID, 256, SM_TOTAL_B>>>(0, nrows, ntiles, src, dst, E);
    aggregate<true><<<agg_blocks, 256>>>(B[0], nullptr, nrows);
    // Layer 2
    gemm_mma<false><<<GEMM_GRID, 256, SM_TOTAL_B>>>(1, nrows, ntiles, src, dst, E);
    aggregate<true><<<agg_blocks, 256>>>(B[1], nullptr, nrows);
    // Layer 3
    gemm_mma<false><<<GEMM_GRID, 256, SM_TOTAL_B>>>(2, nrows, ntiles, src, dst, E);
    aggregate<false><<<agg_blocks, 256>>>(B[2], (float*)d_out, nrows);
}

// round 17
// speedup vs baseline: 1.0136x; 1.0136x over previous
#include <cuda_runtime.h>
#include <cuda_bf16.h>
#include <cstdint>

#define N_MAX 100000
#define E_MAX 1700000
#define D 128
#define BB 1024
#define NB_MAX 128      // >= ceil(N_MAX/BB) = 98

// ---------------- scratch (static device globals) ----------------
__device__ __align__(16) float g_buf[N_MAX * D];            // g[u] = dinv[u]*(X@W)[u]
__device__ __align__(16) __nv_bfloat16 g_xh[N_MAX * D];     // activation hi split
__device__ __align__(16) __nv_bfloat16 g_xl[N_MAX * D];     // activation lo split
__device__ float g_dinv[N_MAX];
__device__ int   g_cnt[N_MAX];                              // ZERO on entry (re-zeroed by fill_csr)
__device__ int   g_rank[E_MAX];                             // edge rank within dst bucket
__device__ int   g_rowptr[N_MAX + 1];
__device__ int   g_blocksum[NB_MAX];
__device__ int   g_blockoff[NB_MAX];
__device__ int   g_csr[E_MAX];
__device__ __align__(16) __nv_bfloat16 g_wt_hi[3 * D * D];  // W^T hi split [l][n][k]
__device__ __align__(16) __nv_bfloat16 g_wt_lo[3 * D * D];  // W^T lo split
__device__ unsigned g_bar_cnt = 0;
__device__ unsigned g_bar_gen = 0;

// ---------------- helpers ----------------
__device__ __forceinline__ uint32_t smem_u32(const void* p) {
    uint32_t a;
    asm("{ .reg .u64 t; cvta.to.shared.u64 t, %1; cvt.u32.u64 %0, t; }" : "=r"(a) : "l"(p));
    return a;
}
__device__ __forceinline__ void cp_async16(uint32_t saddr, const void* gptr, bool valid) {
    int sz = valid ? 16 : 0;
    asm volatile("cp.async.cg.shared.global [%0], [%1], 16, %2;"
                 :: "r"(saddr), "l"(gptr), "r"(sz));
}
#define CP_COMMIT()    asm volatile("cp.async.commit_group;")
#define CP_WAIT_ALL()  asm volatile("cp.async.wait_all;" ::: "memory")
#define CP_WAIT_1()    asm volatile("cp.async.wait_group 1;" ::: "memory")

__device__ __forceinline__ void ldsm_x4(uint32_t* r, uint32_t saddr) {
    asm volatile("ldmatrix.sync.aligned.m8n8.x4.shared.b16 {%0,%1,%2,%3}, [%4];"
                 : "=r"(r[0]), "=r"(r[1]), "=r"(r[2]), "=r"(r[3]) : "r"(saddr));
}

__device__ __forceinline__ void split_store(float x, float y, float z, float w,
                                            __nv_bfloat16* ph, __nv_bfloat16* pl) {
    __nv_bfloat162 h01, h23, l01, l23;
    h01.x = __float2bfloat16(x); h01.y = __float2bfloat16(y);
    h23.x = __float2bfloat16(z); h23.y = __float2bfloat16(w);
    l01.x = __float2bfloat16(x - __bfloat162float(h01.x));
    l01.y = __float2bfloat16(y - __bfloat162float(h01.y));
    l23.x = __float2bfloat16(z - __bfloat162float(h23.x));
    l23.y = __float2bfloat16(w - __bfloat162float(h23.y));
    *(uint2*)ph = make_uint2(*(uint32_t*)&h01, *(uint32_t*)&h23);
    *(uint2*)pl = make_uint2(*(uint32_t*)&l01, *(uint32_t*)&l23);
}

// sense-reversing grid barrier; single-wave residency required
__device__ __forceinline__ void grid_barrier(int nblocks) {
    __syncthreads();
    if (threadIdx.x == 0) {
        unsigned gen = atomicAdd(&g_bar_gen, 0u);
        __threadfence();
        unsigned old = atomicAdd(&g_bar_cnt, 1u);
        if (old == (unsigned)nblocks - 1u) {
            atomicExch(&g_bar_cnt, 0u);
            __threadfence();
            atomicAdd(&g_bar_gen, 1u);
        } else {
            while (atomicAdd(&g_bar_gen, 0u) == gen) { }
        }
        __threadfence();
    }
    __syncthreads();
}

// ---------------- fused prep: W/X splits + degree histogram (+ edge ranks) ----------------
__global__ void prep_cnt(const float* __restrict__ X,
                         const float* __restrict__ W0, const float* __restrict__ W1,
                         const float* __restrict__ W2,
                         const int* __restrict__ dst, int n, int E) {
    int gi  = blockIdx.x * blockDim.x + threadIdx.x;
    int gsz = gridDim.x * blockDim.x;
    int total4 = n * (D / 4);
    for (int i = gi; i < total4; i += gsz) {
        float4 v = *(const float4*)&X[(size_t)i * 4];
        split_store(v.x, v.y, v.z, v.w, &g_xh[(size_t)i * 4], &g_xl[(size_t)i * 4]);
    }
    for (int i = gi; i < 3 * D * D; i += gsz) {
        int l = i / (D * D);
        int r = i % (D * D);
        int nn = r >> 7, kk = r & 127;
        const float* W = (l == 0) ? W0 : ((l == 1) ? W1 : W2);
        float f = W[kk * D + nn];
        __nv_bfloat16 h = __float2bfloat16(f);
        g_wt_hi[i] = h;
        g_wt_lo[i] = __float2bfloat16(f - __bfloat162float(h));
    }
    for (int i = gi; i < E; i += gsz) {
        int d = __ldg(&dst[i]);
        g_rank[i] = atomicAdd(&g_cnt[d], 1);   // rank within dst bucket (free byproduct)
    }
}

// ---------------- fused scan: rowptr/dinv ----------------
__global__ __launch_bounds__(BB)
void scan_all(int n, int nblocks) {
    __shared__ int s[BB];
    __shared__ int s2[NB_MAX];
    const int tid = threadIdx.x;
    const int b   = blockIdx.x;
    const int gi  = b * BB + tid;

    int v = (gi < n) ? g_cnt[gi] : 0;
    s[tid] = v;
    __syncthreads();
    #pragma unroll
    for (int off = 1; off < BB; off <<= 1) {
        int t = (tid >= off) ? s[tid - off] : 0;
        __syncthreads();
        s[tid] += t;
        __syncthreads();
    }
    int incl = s[tid];
    if (tid == BB - 1) g_blocksum[b] = incl;
    grid_barrier(nblocks);

    if (b == 0) {
        int u = (tid < nblocks) ? g_blocksum[tid] : 0;
        if (tid < NB_MAX) s2[tid] = u;
        __syncthreads();
        #pragma unroll
        for (int off = 1; off < NB_MAX; off <<= 1) {
            int t = (tid >= off && tid < NB_MAX) ? s2[tid - off] : 0;
            __syncthreads();
            if (tid < NB_MAX) s2[tid] += t;
            __syncthreads();
        }
        if (tid < nblocks) g_blockoff[tid] = s2[tid] - u;
        if (tid == nblocks - 1) g_rowptr[n] = s2[tid];
    }
    grid_barrier(nblocks);

    if (gi < n) {
        int excl = incl - v + g_blockoff[b];
        g_rowptr[gi] = excl;
        g_dinv[gi]   = rsqrtf((float)(v + 1));
    }
}

// ---------------- CSR fill: atomic-free via precomputed ranks; re-zero cnt ----------------
__global__ void fill_csr(const int* __restrict__ src, const int* __restrict__ dst,
                         int E, int n) {
    int i = blockIdx.x * blockDim.x + threadIdx.x;
    if (i < E) {
        int d = __ldg(&dst[i]);
        g_csr[g_rowptr[d] + g_rank[i]] = __ldg(&src[i]);
    }
    if (i < n) g_cnt[i] = 0;   // cnt dead now; next call starts from zero
}

// ---------------- persistent bf16x3 GEMM: ldmatrix + split-fused loop ----------------
#define PITCH 68
#define AR 32
#define SM_B (128 * PITCH)
#define SM_A (AR * PITCH)
#define SM_TOTAL_B ((2 * SM_B + 4 * SM_A) * 4)   // 104448 bytes -> 2 CTAs/SM
#define GEMM_GRID 296

__device__ __forceinline__ void mma16816(float* c, const uint32_t* a, const uint32_t* b) {
    asm volatile(
        "mma.sync.aligned.m16n8k16.row.col.f32.bf16.bf16.f32 "
        "{%0,%1,%2,%3}, {%4,%5,%6,%7}, {%8,%9}, {%0,%1,%2,%3};"
        : "+f"(c[0]), "+f"(c[1]), "+f"(c[2]), "+f"(c[3])
        : "r"(a[0]), "r"(a[1]), "r"(a[2]), "r"(a[3]), "r"(b[0]), "r"(b[1]));
}

__global__ __launch_bounds__(256, 2)
void gemm_mma(int layer, int nrows, int ntiles) {
    extern __shared__ uint32_t smem[];
    uint32_t* Bh = smem;
    uint32_t* Bl = Bh + SM_B;

    const int tid = threadIdx.x;
    const uint32_t sb  = smem_u32(smem);
    const uint32_t sBh = sb;
    const uint32_t sBl = sb + SM_B * 4;
    const uint32_t sA  = sb + 2 * SM_B * 4;

    {
        const __nv_bfloat16* wh = &g_wt_hi[layer * D * D];
        const __nv_bfloat16* wl = &g_wt_lo[layer * D * D];
        #pragma unroll
        for (int i = 0; i < 8; i++) {
            int id = tid + i * 256;
            int n  = id >> 4;
            int q  = id & 15;
            size_t gof = (size_t)n * D + q * 8;
            uint32_t so = (n * PITCH + q * 4) * 4;
            cp_async16(sBh + so, &wh[gof], true);
            cp_async16(sBl + so, &wl[gof], true);
        }
    }
    CP_COMMIT();

    auto loadA = [&](int buf, int t) {
        int m0 = t * AR;
        uint32_t base = sA + (uint32_t)buf * (2 * SM_A * 4);
        #pragma unroll
        for (int i = 0; i < 2; i++) {
            int id  = tid + i * 256;
            int row = id >> 4;
            int q   = id & 15;
            int gr  = m0 + row;
            bool ok = gr < nrows;
            size_t gof = (size_t)gr * D + q * 8;
            uint32_t so = (row * PITCH + q * 4) * 4;
            cp_async16(base + so, &g_xh[gof], ok);
            cp_async16(base + SM_A * 4 + so, &g_xl[gof], ok);
        }
    };

    const int t0     = blockIdx.x;
    const int stride = gridDim.x;
    if (t0 < ntiles) loadA(0, t0);
    CP_COMMIT();

    const int wid  = tid >> 5;
    const int lane = tid & 31;
    const int g    = lane >> 2;
    const int tig  = lane & 3;
    const int wn   = wid * 16;

    const int lm_m   = lane >> 3;
    const int lm_row = ((lm_m & 1) << 3) + (lane & 7);
    const int lm_kc  = (lm_m >> 1) << 2;
    const uint32_t lm_off = (uint32_t)(lm_row * PITCH + lm_kc) * 4;

    CP_WAIT_1();
    __syncthreads();

    uint32_t breg[2][8][2][2];
    #pragma unroll
    for (int sp = 0; sp < 2; sp++) {
        const uint32_t* Bp = sp ? Bl : Bh;
        #pragma unroll
        for (int step = 0; step < 8; step++) {
            #pragma unroll
            for (int nt = 0; nt < 2; nt++) {
                int c = wn + nt * 8 + g;
                breg[sp][step][nt][0] = Bp[c * PITCH + step * 8 + tig];
                breg[sp][step][nt][1] = Bp[c * PITCH + step * 8 + tig + 4];
            }
        }
    }

    int buf = 0;
    for (int t = t0; t < ntiles; t += stride) {
        int nxt = t + stride;
        if (nxt < ntiles) loadA(buf ^ 1, nxt);
        CP_COMMIT();
        CP_WAIT_1();
        __syncthreads();

        const uint32_t aHi = sA + (uint32_t)buf * (2 * SM_A * 4) + lm_off;
        const uint32_t aLo = aHi + SM_A * 4;

        float acc[2][2][4];
        #pragma unroll
        for (int mt = 0; mt < 2; mt++)
            #pragma unroll
            for (int nt = 0; nt < 2; nt++)
                #pragma unroll
                for (int e = 0; e < 4; e++) acc[mt][nt][e] = 0.f;

        #pragma unroll
        for (int step = 0; step < 8; step++) {
            const uint32_t koff = (uint32_t)(step * 8) * 4;
            uint32_t ah[2][4], al[2][4];
            #pragma unroll
            for (int mt = 0; mt < 2; mt++)
                ldsm_x4(ah[mt], aHi + (uint32_t)(mt * 16 * PITCH) * 4 + koff);
            #pragma unroll
            for (int mt = 0; mt < 2; mt++)
                ldsm_x4(al[mt], aLo + (uint32_t)(mt * 16 * PITCH) * 4 + koff);
            #pragma unroll
            for (int mt = 0; mt < 2; mt++) {
                #pragma unroll
                for (int nt = 0; nt < 2; nt++) {
                    mma16816(acc[mt][nt], ah[mt], breg[0][step][nt]);
                    mma16816(acc[mt][nt], ah[mt], breg[1][step][nt]);
                    mma16816(acc[mt][nt], al[mt], breg[0][step][nt]);
                }
            }
        }

        int m0 = t * AR;
        #pragma unroll
        for (int mt = 0; mt < 2; mt++) {
            #pragma unroll
            for (int half = 0; half < 2; half++) {
                int row = m0 + mt * 16 + g + half * 8;
                if (row < nrows) {
                    float dv = g_dinv[row];
                    #pragma unroll
                    for (int nt = 0; nt < 2; nt++) {
                        float2 v;
                        v.x = dv * acc[mt][nt][half * 2 + 0];
                        v.y = dv * acc[mt][nt][half * 2 + 1];
                        *(float2*)&g_buf[(size_t)row * D + wn + nt * 8 + tig * 2] = v;
                    }
                }
            }
        }
        __syncthreads();
        buf ^= 1;
    }
    CP_WAIT_ALL();
}

// ---------------- aggregate (unroll x8) ----------------
template <bool TO_GX>
__global__ __launch_bounds__(256)
void aggregate(const float* __restrict__ bias, float* __restrict__ outp, int n) {
    int w    = (blockIdx.x * blockDim.x + threadIdx.x) >> 5;
    int lane = threadIdx.x & 31;
    if (w >= n) return;

    int beg = g_rowptr[w];
    int end = g_rowptr[w + 1];
    size_t col = (size_t)lane * 4;

    float4 acc = *(const float4*)&g_buf[(size_t)w * D + col];   // self-loop

    int e = beg;
    for (; e + 8 <= end; e += 8) {
        int s[8];
        #pragma unroll
        for (int j = 0; j < 8; j++) s[j] = __ldg(&g_csr[e + j]);
        float4 v[8];
        #pragma unroll
        for (int j = 0; j < 8; j++) v[j] = *(const float4*)&g_buf[(size_t)s[j] * D + col];
        #pragma unroll
        for (int j = 0; j < 8; j++) {
            acc.x += v[j].x; acc.y += v[j].y; acc.z += v[j].z; acc.w += v[j].w;
        }
    }
    for (; e + 2 <= end; e += 2) {
        int s0 = __ldg(&g_csr[e]);
        int s1 = __ldg(&g_csr[e + 1]);
        float4 v0 = *(const float4*)&g_buf[(size_t)s0 * D + col];
        float4 v1 = *(const float4*)&g_buf[(size_t)s1 * D + col];
        acc.x += v0.x + v1.x;
        acc.y += v0.y + v1.y;
        acc.z += v0.z + v1.z;
        acc.w += v0.w + v1.w;
    }
    if (e < end) {
        int s0 = __ldg(&g_csr[e]);
        float4 v0 = *(const float4*)&g_buf[(size_t)s0 * D + col];
        acc.x += v0.x; acc.y += v0.y; acc.z += v0.z; acc.w += v0.w;
    }

    float dv = g_dinv[w];
    float4 b = *(const float4*)&bias[col];
    float4 r;
    r.x = fmaxf(fmaf(dv, acc.x, b.x), 0.f);
    r.y = fmaxf(fmaf(dv, acc.y, b.y), 0.f);
    r.z = fmaxf(fmaf(dv, acc.z, b.z), 0.f);
    r.w = fmaxf(fmaf(dv, acc.w, b.w), 0.f);

    if (TO_GX) {
        size_t off = (size_t)w * D + col;
        split_store(r.x, r.y, r.z, r.w, &g_xh[off], &g_xl[off]);
    } else {
        *(float4*)&outp[(size_t)w * D + col] = r;
    }
}

// ---------------- launch ----------------
extern "C" void kernel_launch(void* const* d_in, const int* in_sizes, int n_in,
                              void* d_out, int out_size) {
    const float* node_fts = (const float*)d_in[0];
    const int*   edge     = (const int*)d_in[1];   // int32
    const float* W[3] = { (const float*)d_in[2], (const float*)d_in[4], (const float*)d_in[6] };
    const float* B[3] = { (const float*)d_in[3], (const float*)d_in[5], (const float*)d_in[7] };

    const int nrows = in_sizes[0] / D;
    const int E     = in_sizes[1] / 2;
    const int* src  = edge;
    const int* dst  = edge + E;

    static bool attr_done = false;
    if (!attr_done) {
        cudaFuncSetAttribute(gemm_mma, cudaFuncAttributeMaxDynamicSharedMemorySize, SM_TOTAL_B);
        attr_done = true;
    }

    const int nblocks = (nrows + BB - 1) / BB;

    // build: 3 launches (fill now atomic-free via ranks)
    prep_cnt<<<(nrows * (D / 4) + 255) / 256, 256>>>(node_fts, W[0], W[1], W[2], dst, nrows, E);
    scan_all<<<nblocks, BB>>>(nrows, nblocks);
    fill_csr<<<(E + 255) / 256, 256>>>(src, dst, E, nrows);

    const int ntiles     = (nrows + AR - 1) / AR;
    const int agg_blocks = (nrows * 32 + 255) / 256;

    // Layer 1
    gemm_mma<<<GEMM_GRID, 256, SM_TOTAL_B>>>(0, nrows, ntiles);
    aggregate<true><<<agg_blocks, 256>>>(B[0], nullptr, nrows);
    // Layer 2
    gemm_mma<<<GEMM_GRID, 256, SM_TOTAL_B>>>(1, nrows, ntiles);
    aggregate<true><<<agg_blocks, 256>>>(B[1], nullptr, nrows);
    // Layer 3
    gemm_mma<<<GEMM_GRID, 256, SM_TOTAL_B>>>(2, nrows, ntiles);
    aggregate<false><<<agg_blocks, 256>>>(B[2], (float*)d_out, nrows);
}